// round 16
// baseline (speedup 1.0000x reference)
#include <cuda_runtime.h>
#include <cuda_bf16.h>
#include <string.h>

// Problem constants (static shapes from the reference)
#define NPTS   32768          // 8 * 4096 points (contiguous in output)
#define NROWS  4096           // 64 * 64 (m,n) pairs
#define NBASIS 23
#define KP     24             // padded K (23 + 1 zero slot), 12 f32x2 pairs

// Scratch: poly p-major [p][24] so {poly[2j],poly[2j+1]} is a natural
// aligned 64-bit pair (zero packing in the GEMM inner loop).
__device__ __align__(16) float g_poly2[(size_t)NPTS * KP];

// ---------------------------------------------------------------------------
// Kernel 1: per-point hydrogen wavefunction basis (validated rel_err 1.2e-7).
// ---------------------------------------------------------------------------
__global__ void basis_kernel(const float* __restrict__ pos) {
    int p = blockIdx.x * blockDim.x + threadIdx.x;
    if (p >= NPTS) return;

    float x = pos[3 * p + 0], y = pos[3 * p + 1], z = pos[3 * p + 2];
    float r    = sqrtf(x * x + y * y + z * z) + 1e-12f;
    float invr = 1.0f / r;
    float xs = x * invr, ys = y * invr, ct = z * invr;

    float e1 = expf(-r), e2 = expf(-0.5f * r);
    float e3 = expf(-r * (1.0f / 3.0f)), e4 = expf(-0.25f * r);

    const float C00 = 0.28209479177387814f;
    const float K10 = 0.4886025119029199f;
    const float C21 = 1.0925484305920792f;
    const float C22 = 0.5462742152960396f;
    const float C20 = 0.31539156525252005f;

    float Y1m1 = -K10 * ys, Y10 = K10 * ct, Y1p1 = -K10 * xs;
    float Y2m2 =  C21 * xs * ys;
    float Y2m1 = -C21 * ys * ct;
    float Y20  =  C20 * (3.0f * ct * ct - 1.0f);
    float Y2p1 = -C21 * xs * ct;
    float Y2p2 =  C22 * (xs * xs - ys * ys);

    float R10 = 2.0f * e1;
    float R20 = 0.35355339059327373f * e2 * (2.0f - r);
    float R21 = 0.2041241452319315f  * e2 * r;

    float rho3 = (2.0f / 3.0f) * r;
    float R30 = 0.1283000598199168f   * e3 * (3.0f - 3.0f * rho3 + 0.5f * rho3 * rho3);
    float R31 = 0.045360921162019494f * e3 * rho3 * (4.0f - rho3);
    float R32 = 0.02028602242947916f  * e3 * rho3 * rho3;

    float rho4 = 0.5f * r;
    float R40 = 0.0625f * e4 *
                (4.0f - 6.0f * rho4 + 2.0f * rho4 * rho4 - rho4 * rho4 * rho4 * (1.0f / 6.0f));
    float R41 = 0.016137430609197573f * e4 * rho4 * (10.0f - 5.0f * rho4 + 0.5f * rho4 * rho4);
    float R42 = 0.004658474194686761f * e4 * rho4 * rho4 * (6.0f - rho4);

    float v[KP];
    v[0]  = R10 * C00;
    v[1]  = R20 * C00;
    v[2]  = R21 * Y1m1;  v[3]  = R21 * Y10;  v[4]  = R21 * Y1p1;
    v[5]  = R30 * C00;
    v[6]  = R31 * Y1m1;  v[7]  = R31 * Y10;  v[8]  = R31 * Y1p1;
    v[9]  = R32 * Y2m2;  v[10] = R32 * Y2m1; v[11] = R32 * Y20;
    v[12] = R32 * Y2p1;  v[13] = R32 * Y2p2;
    v[14] = R40 * C00;
    v[15] = R41 * Y1m1;  v[16] = R41 * Y10;  v[17] = R41 * Y1p1;
    v[18] = R42 * Y2m2;  v[19] = R42 * Y2m1; v[20] = R42 * Y20;
    v[21] = R42 * Y2p1;  v[22] = R42 * Y2p2;
    v[23] = 0.0f;                              // pad slot MUST be zero

    float4* dst = reinterpret_cast<float4*>(g_poly2 + (size_t)p * KP);
    const float4* src = reinterpret_cast<const float4*>(v);
#pragma unroll
    for (int i = 0; i < KP / 4; i++) dst[i] = src[i];
}

// ---------------------------------------------------------------------------
// Kernel 2: out(4096 x 32768) = coeff(4096 x 23) @ poly(23 x 32768)
// f32x2 GEMM with K SPLIT ACROSS LANES (zero duplication MOVs):
//   acc[pt] = { sum over even k, sum over odd k };  out = lo(acc) + hi(acc)
//   - poly pairs {p[2j],p[2j+1]} register-resident (p-major layout, natural
//     64-bit alignment) — no packing ever
//   - coeff pairs {c_r[2j],c_r[2j+1]} read directly as ulonglong2 halves from
//     r-major smem (6 broadcast LDS.128 per row -> 48 fma2)
//   - W=4 adjacent points/thread -> one STG.128 per row; 16 warps/SM
// ---------------------------------------------------------------------------
#define TPB   256
#define PT    1024   // points per block (4 adjacent per thread)
#define RT    128    // coefficient rows per block

typedef unsigned long long ull;

__device__ __forceinline__ void fma2(ull& acc, ull a, ull b) {
    asm("fma.rn.f32x2 %0, %1, %2, %0;" : "+l"(acc) : "l"(a), "l"(b));
}
__device__ __forceinline__ float hsum2(ull u) {
    float lo, hi;
    asm("mov.b64 {%0, %1}, %2;" : "=f"(lo), "=f"(hi) : "l"(u));
    return lo + hi;
}

__global__ __launch_bounds__(TPB, 2) void gemm_kernel(const float* __restrict__ coeff,
                                                      float* __restrict__ out) {
    __shared__ __align__(16) float cs[RT * KP];   // r-major: cs[row][24], 12 KB

    int tid = threadIdx.x;
    int p0  = blockIdx.x * PT + 4 * tid;  // four adjacent points p0..p0+3
    int r0  = blockIdx.y * RT;

    // Stage coefficient tile r-major, pad slot zeroed.
    for (int i = tid; i < RT * KP; i += TPB) {
        int rr = i / KP;
        int k  = i - rr * KP;
        cs[i] = (k < NBASIS) ? coeff[(r0 + rr) * NBASIS + k] : 0.0f;
    }

    // Poly pairs for this thread's 4 points: 4 x 12 ull = 96 regs, loaded as
    // coalesced ulonglong2 (each thread reads 4 x 96 B contiguous).
    ull pp[4][12];
#pragma unroll
    for (int i = 0; i < 4; i++) {
        const ulonglong2* src =
            reinterpret_cast<const ulonglong2*>(g_poly2 + (size_t)(p0 + i) * KP);
#pragma unroll
        for (int j = 0; j < 6; j++) {
            ulonglong2 t = src[j];
            pp[i][2 * j]     = t.x;
            pp[i][2 * j + 1] = t.y;
        }
    }
    __syncthreads();

    float* ob = out + (size_t)r0 * NPTS + p0;
    for (int rj = 0; rj < RT; rj++) {
        const ulonglong2* cq = reinterpret_cast<const ulonglong2*>(cs + rj * KP);
        ull a0 = 0ull, a1 = 0ull, a2 = 0ull, a3 = 0ull;
#pragma unroll
        for (int kk = 0; kk < 6; kk++) {
            ulonglong2 c2 = cq[kk];          // broadcast LDS.128: k-pairs 2kk, 2kk+1
            fma2(a0, c2.x, pp[0][2 * kk]);   fma2(a0, c2.y, pp[0][2 * kk + 1]);
            fma2(a1, c2.x, pp[1][2 * kk]);   fma2(a1, c2.y, pp[1][2 * kk + 1]);
            fma2(a2, c2.x, pp[2][2 * kk]);   fma2(a2, c2.y, pp[2][2 * kk + 1]);
            fma2(a3, c2.x, pp[3][2 * kk]);   fma2(a3, c2.y, pp[3][2 * kk + 1]);
        }
        float4 o = make_float4(hsum2(a0), hsum2(a1), hsum2(a2), hsum2(a3));
        __stcs(reinterpret_cast<float4*>(ob), o);    // streaming STG.128
        ob += NPTS;
    }
}

// ---------------------------------------------------------------------------
// Launch: [0] position (8*4096*3 f32), [1] coefficients (64*64*23 f32).
// Output: (64,64,8,4096) f32 = out[row][point].
// ---------------------------------------------------------------------------
extern "C" void kernel_launch(void* const* d_in, const int* in_sizes, int n_in,
                              void* d_out, int out_size) {
    const float* pos   = (const float*)d_in[0];
    const float* coeff = (const float*)d_in[1];
    float* out = (float*)d_out;

    basis_kernel<<<NPTS / 256, 256>>>(pos);

    dim3 grid(NPTS / PT, NROWS / RT);   // (32, 32)
    gemm_kernel<<<grid, TPB>>>(coeff, out);
}